// round 3
// baseline (speedup 1.0000x reference)
#include <cuda_runtime.h>
#include <cuda_bf16.h>
#include <cstdint>

#define HID      128
#define NNODES   50000
#define NEDGES   640000
#define NLAYERS  6

// ---------------- scratch (device globals: no allocation allowed) ----------
__device__ float g_x[(size_t)NNODES * HID];      // node features
__device__ float g_sum[(size_t)NNODES * HID];    // scatter-sum accumulator
__device__ float g_ef[(size_t)NEDGES * HID];     // edge features
__device__ float g_cnt[NNODES];                  // in-degree
__device__ float g_cntinv[NNODES];               // 1/max(deg,1)
__device__ int   g_src[NEDGES];                  // normalized int32 indices
__device__ int   g_dst[NEDGES];
__device__ unsigned int g_idx_is_i32;            // dtype flag

// ---------------- zero-fill (memset nodes invalid on device globals) --------
__global__ void zero_kernel() {
    size_t i = (size_t)blockIdx.x * blockDim.x + threadIdx.x;
    size_t n4 = (size_t)NNODES * HID / 4;
    if (i < n4) {
        ((float4*)g_x)[i]   = make_float4(0.f, 0.f, 0.f, 0.f);
        ((float4*)g_sum)[i] = make_float4(0.f, 0.f, 0.f, 0.f);
    }
    if (i < NNODES) g_cnt[i] = 0.0f;
    if (i == 0)     g_idx_is_i32 = 0u;
}

// ---------------- edge_index dtype detection + normalization ----------------
// Reads only the first 2*NEDGES int32 words (valid under either dtype).
// int64 data: words at odd positions are hi-halves of values < 2^32 -> all 0.
// int32 data: odd words are random indices in [0,50000) -> some nonzero.
__global__ void detect_idx_kernel(const unsigned int* __restrict__ w) {
    int i = blockIdx.x * blockDim.x + threadIdx.x;      // odd-word index
    unsigned int v = w[2 * i + 1];
    if (v != 0u) atomicOr(&g_idx_is_i32, 1u);
}

__global__ void convert_idx_kernel(const void* __restrict__ ei) {
    int e = blockIdx.x * blockDim.x + threadIdx.x;
    if (e >= NEDGES) return;
    if (g_idx_is_i32) {
        const int* p = (const int*)ei;
        g_src[e] = p[e];
        g_dst[e] = p[NEDGES + e];
    } else {
        const long long* p = (const long long*)ei;
        g_src[e] = (int)p[e];
        g_dst[e] = (int)p[NEDGES + e];
    }
}

// ---------------- packed f32x2 helpers -------------------------------------
__device__ __forceinline__ void ffma2(unsigned long long& acc,
                                      unsigned long long a,
                                      unsigned long long b) {
    asm("fma.rn.f32x2 %0, %1, %2, %0;" : "+l"(acc) : "l"(a), "l"(b));
}
__device__ __forceinline__ unsigned long long dup2(float x) {
    unsigned long long r;
    asm("mov.b64 %0, {%1, %1};" : "=l"(r) : "f"(x));
    return r;
}
__device__ __forceinline__ float2 unpack2(unsigned long long v) {
    float2 f;
    asm("mov.b64 {%0, %1}, %2;" : "=f"(f.x), "=f"(f.y) : "l"(v));
    return f;
}

// ---------------- 64x128 += Asm[64x128] @ Wsm[128x128] ----------------------
// Thread (ty in 0..7, tx in 0..31) owns rows ty*8..ty*8+7, cols tx*4..tx*4+3.
__device__ __forceinline__ void gemm128(unsigned long long acc[8][2],
                                        const float* Asm, const float* Wsm,
                                        int ty, int tx) {
    const float4*      A4  = (const float4*)Asm;
    const ulonglong2*  W2v = (const ulonglong2*)Wsm;
    #pragma unroll 4
    for (int k = 0; k < 128; k += 4) {
        ulonglong2 w[4];
        #pragma unroll
        for (int kk = 0; kk < 4; kk++) w[kk] = W2v[(k + kk) * 32 + tx];
        #pragma unroll
        for (int e = 0; e < 8; e++) {
            float4 a = A4[(ty * 8 + e) * 32 + (k >> 2)];
            unsigned long long ap;
            ap = dup2(a.x); ffma2(acc[e][0], ap, w[0].x); ffma2(acc[e][1], ap, w[0].y);
            ap = dup2(a.y); ffma2(acc[e][0], ap, w[1].x); ffma2(acc[e][1], ap, w[1].y);
            ap = dup2(a.z); ffma2(acc[e][0], ap, w[2].x); ffma2(acc[e][1], ap, w[2].y);
            ap = dup2(a.w); ffma2(acc[e][0], ap, w[3].x); ffma2(acc[e][1], ap, w[3].y);
        }
    }
}

// ---------------- encoder: ef = edge_attr @ enc_w + enc_b ------------------
__global__ void encode_kernel(const float* __restrict__ ea,
                              const float* __restrict__ w,
                              const float* __restrict__ b) {
    int gid = blockIdx.x * 256 + threadIdx.x;   // NEDGES*32 threads exactly
    int e = gid >> 5, q = gid & 31;
    if (e >= NEDGES) return;
    float a0 = __ldg(ea + (size_t)e * 3 + 0);
    float a1 = __ldg(ea + (size_t)e * 3 + 1);
    float a2 = __ldg(ea + (size_t)e * 3 + 2);
    float4 w0 = __ldg((const float4*)w + q);
    float4 w1 = __ldg((const float4*)(w + 128) + q);
    float4 w2 = __ldg((const float4*)(w + 256) + q);
    float4 bb = __ldg((const float4*)b + q);
    float4 r;
    r.x = bb.x + a0 * w0.x + a1 * w1.x + a2 * w2.x;
    r.y = bb.y + a0 * w0.y + a1 * w1.y + a2 * w2.y;
    r.z = bb.z + a0 * w0.z + a1 * w1.z + a2 * w2.z;
    r.w = bb.w + a0 * w0.w + a1 * w1.w + a2 * w2.w;
    ((float4*)g_ef)[(size_t)e * 32 + q] = r;
}

// ---------------- in-degree -------------------------------------------------
__global__ void degree_kernel() {
    int e = blockIdx.x * 256 + threadIdx.x;
    if (e < NEDGES) {
        int d = g_dst[e];
        if (d >= 0 && d < NNODES) atomicAdd(&g_cnt[d], 1.0f);
    }
}
__global__ void cntinv_kernel() {
    int n = blockIdx.x * 256 + threadIdx.x;
    if (n < NNODES) g_cntinv[n] = 1.0f / fmaxf(g_cnt[n], 1.0f);
}

// ---------------- fused edge MLP + residual + scatter -----------------------
// input = [x[dst] | x[src] | ef]  (3 K-chunks of 128)
__global__ void __launch_bounds__(256, 2)
edge_kernel(const float* __restrict__ w1, const float* __restrict__ b1,
            const float* __restrict__ w2, const float* __restrict__ b2) {
    extern __shared__ float sm[];
    float* Asm = sm;            // 64*128 floats (also reused for hidden H)
    float* Wsm = sm + 8192;     // 128*128 floats
    __shared__ int   s_src[64], s_dst[64];
    __shared__ float s_b1[128], s_b2[128];

    int tid = threadIdx.x, ty = tid >> 5, tx = tid & 31;
    int e0 = blockIdx.x * 64;

    if (tid < 64) {
        s_src[tid] = g_src[e0 + tid];
        s_dst[tid] = g_dst[e0 + tid];
    }
    if (tid < 128) { s_b1[tid] = b1[tid]; s_b2[tid] = b2[tid]; }

    unsigned long long acc[8][2];
    #pragma unroll
    for (int e = 0; e < 8; e++) { acc[e][0] = 0ull; acc[e][1] = 0ull; }

    // ---- GEMM1: 3 chunks over K=384
    for (int c = 0; c < 3; c++) {
        __syncthreads();
        #pragma unroll
        for (int i = 0; i < 8; i++) {           // A tile: 2048 float4
            int lin = tid + i * 256;
            int r = lin >> 5, col = lin & 31;
            float4 v;
            if (c == 0)      v = ((const float4*)(g_x  + (size_t)s_dst[r] * HID))[col];
            else if (c == 1) v = ((const float4*)(g_x  + (size_t)s_src[r] * HID))[col];
            else             v = ((const float4*)(g_ef + (size_t)(e0 + r) * HID))[col];
            ((float4*)Asm)[lin] = v;
        }
        const float4* wg = (const float4*)(w1 + (size_t)c * 128 * HID);
        #pragma unroll
        for (int i = 0; i < 16; i++) {          // W tile: 4096 float4
            int lin = tid + i * 256;
            ((float4*)Wsm)[lin] = wg[lin];
        }
        __syncthreads();
        gemm128(acc, Asm, Wsm, ty, tx);
    }
    __syncthreads();

    // ---- bias + relu -> H in smem (reuse Asm)
    #pragma unroll
    for (int e = 0; e < 8; e++) {
        float2 p0 = unpack2(acc[e][0]), p1 = unpack2(acc[e][1]);
        float4 h;
        h.x = fmaxf(p0.x + s_b1[tx * 4 + 0], 0.0f);
        h.y = fmaxf(p0.y + s_b1[tx * 4 + 1], 0.0f);
        h.z = fmaxf(p1.x + s_b1[tx * 4 + 2], 0.0f);
        h.w = fmaxf(p1.y + s_b1[tx * 4 + 3], 0.0f);
        ((float4*)Asm)[(ty * 8 + e) * 32 + tx] = h;
        acc[e][0] = 0ull; acc[e][1] = 0ull;
    }
    #pragma unroll
    for (int i = 0; i < 16; i++) {              // W2 tile
        int lin = tid + i * 256;
        ((float4*)Wsm)[lin] = ((const float4*)w2)[lin];
    }
    __syncthreads();

    // ---- GEMM2: K=128
    gemm128(acc, Asm, Wsm, ty, tx);

    // ---- epilogue: m = acc + b2 ; ef += m ; scatter-add to g_sum[dst]
    #pragma unroll
    for (int e = 0; e < 8; e++) {
        int le = ty * 8 + e;
        int ge = e0 + le;
        float2 p0 = unpack2(acc[e][0]), p1 = unpack2(acc[e][1]);
        float4 m;
        m.x = p0.x + s_b2[tx * 4 + 0];
        m.y = p0.y + s_b2[tx * 4 + 1];
        m.z = p1.x + s_b2[tx * 4 + 2];
        m.w = p1.y + s_b2[tx * 4 + 3];

        float4* efp = (float4*)(g_ef + (size_t)ge * HID) + tx;
        float4 eo = *efp;
        eo.x += m.x; eo.y += m.y; eo.z += m.z; eo.w += m.w;
        *efp = eo;

        float* sp = g_sum + (size_t)s_dst[le] * HID + tx * 4;
        atomicAdd(sp + 0, m.x);
        atomicAdd(sp + 1, m.y);
        atomicAdd(sp + 2, m.z);
        atomicAdd(sp + 3, m.w);
    }
}

// ---------------- fused node MLP + residual ---------------------------------
// input = [x | mean_aggr]  (2 K-chunks of 128)
// Also re-zeroes the g_sum rows it consumed (saves a full clear per layer).
__global__ void __launch_bounds__(256, 2)
node_kernel(const float* __restrict__ w1, const float* __restrict__ b1,
            const float* __restrict__ w2, const float* __restrict__ b2) {
    extern __shared__ float sm[];
    float* Asm = sm;
    float* Wsm = sm + 8192;
    __shared__ float s_scale[64];
    __shared__ float s_b1[128], s_b2[128];

    int tid = threadIdx.x, ty = tid >> 5, tx = tid & 31;
    int n0 = blockIdx.x * 64;

    if (tid < 64) {
        int n = n0 + tid;
        s_scale[tid] = (n < NNODES) ? g_cntinv[n] : 0.0f;
    }
    if (tid < 128) { s_b1[tid] = b1[tid]; s_b2[tid] = b2[tid]; }

    unsigned long long acc[8][2];
    #pragma unroll
    for (int e = 0; e < 8; e++) { acc[e][0] = 0ull; acc[e][1] = 0ull; }

    for (int c = 0; c < 2; c++) {
        __syncthreads();
        #pragma unroll
        for (int i = 0; i < 8; i++) {
            int lin = tid + i * 256;
            int r = lin >> 5, col = lin & 31;
            int n = n0 + r;
            bool valid = (n < NNODES);
            if (!valid) n = NNODES - 1;
            float4 v;
            if (c == 0) {
                v = ((const float4*)(g_x + (size_t)n * HID))[col];
            } else {
                v = ((const float4*)(g_sum + (size_t)n * HID))[col];
                float s = s_scale[r];
                v.x *= s; v.y *= s; v.z *= s; v.w *= s;
                // consume-and-clear: ready for next layer's scatter
                if (valid)
                    ((float4*)(g_sum + (size_t)n * HID))[col] =
                        make_float4(0.f, 0.f, 0.f, 0.f);
            }
            ((float4*)Asm)[lin] = v;
        }
        const float4* wg = (const float4*)(w1 + (size_t)c * 128 * HID);
        #pragma unroll
        for (int i = 0; i < 16; i++) {
            int lin = tid + i * 256;
            ((float4*)Wsm)[lin] = wg[lin];
        }
        __syncthreads();
        gemm128(acc, Asm, Wsm, ty, tx);
    }
    __syncthreads();

    #pragma unroll
    for (int e = 0; e < 8; e++) {
        float2 p0 = unpack2(acc[e][0]), p1 = unpack2(acc[e][1]);
        float4 h;
        h.x = fmaxf(p0.x + s_b1[tx * 4 + 0], 0.0f);
        h.y = fmaxf(p0.y + s_b1[tx * 4 + 1], 0.0f);
        h.z = fmaxf(p1.x + s_b1[tx * 4 + 2], 0.0f);
        h.w = fmaxf(p1.y + s_b1[tx * 4 + 3], 0.0f);
        ((float4*)Asm)[(ty * 8 + e) * 32 + tx] = h;
        acc[e][0] = 0ull; acc[e][1] = 0ull;
    }
    #pragma unroll
    for (int i = 0; i < 16; i++) {
        int lin = tid + i * 256;
        ((float4*)Wsm)[lin] = ((const float4*)w2)[lin];
    }
    __syncthreads();

    gemm128(acc, Asm, Wsm, ty, tx);

    #pragma unroll
    for (int e = 0; e < 8; e++) {
        int gn = n0 + ty * 8 + e;
        if (gn >= NNODES) continue;
        float2 p0 = unpack2(acc[e][0]), p1 = unpack2(acc[e][1]);
        float4* xp = (float4*)(g_x + (size_t)gn * HID) + tx;
        float4 xo = *xp;
        xo.x += p0.x + s_b2[tx * 4 + 0];
        xo.y += p0.y + s_b2[tx * 4 + 1];
        xo.z += p1.x + s_b2[tx * 4 + 2];
        xo.w += p1.y + s_b2[tx * 4 + 3];
        *xp = xo;
    }
}

// ---------------- decoder + row-normalize -----------------------------------
__global__ void decode_kernel(const float* __restrict__ dw,
                              const float* __restrict__ db,
                              float* __restrict__ out) {
    int warp = (blockIdx.x * blockDim.x + threadIdx.x) >> 5;
    int lane = threadIdx.x & 31;
    if (warp >= NNODES) return;
    const float* xr = g_x + (size_t)warp * HID;
    float a0 = 0.f, a1 = 0.f, a2 = 0.f;
    #pragma unroll
    for (int i = 0; i < 4; i++) {
        int k = lane + i * 32;
        float xv = xr[k];
        a0 += xv * __ldg(dw + k * 3 + 0);
        a1 += xv * __ldg(dw + k * 3 + 1);
        a2 += xv * __ldg(dw + k * 3 + 2);
    }
    #pragma unroll
    for (int o = 16; o; o >>= 1) {
        a0 += __shfl_xor_sync(0xffffffffu, a0, o);
        a1 += __shfl_xor_sync(0xffffffffu, a1, o);
        a2 += __shfl_xor_sync(0xffffffffu, a2, o);
    }
    if (lane == 0) {
        a0 += __ldg(db + 0); a1 += __ldg(db + 1); a2 += __ldg(db + 2);
        float nrm = sqrtf(a0 * a0 + a1 * a1 + a2 * a2);
        float inv = 1.0f / fmaxf(nrm, 1e-12f);
        out[(size_t)warp * 3 + 0] = a0 * inv;
        out[(size_t)warp * 3 + 1] = a1 * inv;
        out[(size_t)warp * 3 + 2] = a2 * inv;
    }
}

// ---------------- launcher ---------------------------------------------------
extern "C" void kernel_launch(void* const* d_in, const int* in_sizes, int n_in,
                              void* d_out, int out_size) {
    (void)in_sizes; (void)n_in; (void)out_size;
    // metadata order: pos, edge_attr, edge_index, enc_w, enc_b, dec_w, dec_b,
    //                 edge_w1, edge_b1, edge_w2, edge_b2,
    //                 node_w1, node_b1, node_w2, node_b2
    const float* edge_attr = (const float*)d_in[1];
    const void*  ei        = d_in[2];
    const float* enc_w = (const float*)d_in[3];
    const float* enc_b = (const float*)d_in[4];
    const float* dec_w = (const float*)d_in[5];
    const float* dec_b = (const float*)d_in[6];
    const float* ew1   = (const float*)d_in[7];
    const float* eb1   = (const float*)d_in[8];
    const float* ew2   = (const float*)d_in[9];
    const float* eb2   = (const float*)d_in[10];
    const float* nw1   = (const float*)d_in[11];
    const float* nb1   = (const float*)d_in[12];
    const float* nw2   = (const float*)d_in[13];
    const float* nb2   = (const float*)d_in[14];

    const int SMEM_BYTES = (8192 + 16384) * sizeof(float);   // 96 KB
    cudaFuncSetAttribute(edge_kernel, cudaFuncAttributeMaxDynamicSharedMemorySize, SMEM_BYTES);
    cudaFuncSetAttribute(node_kernel, cudaFuncAttributeMaxDynamicSharedMemorySize, SMEM_BYTES);
    cudaGetLastError();   // clear any soft error (e.g. attr-set under capture)

    // zero g_x, g_sum, g_cnt, flag
    {
        size_t n4 = (size_t)NNODES * HID / 4;   // 1.6M threads
        zero_kernel<<<(unsigned)((n4 + 255) / 256), 256>>>();
    }

    // detect edge_index dtype (int32 vs int64) and normalize to int32
    detect_idx_kernel<<<NEDGES / 256, 256>>>((const unsigned int*)ei);
    convert_idx_kernel<<<(NEDGES + 255) / 256, 256>>>(ei);

    encode_kernel<<<NEDGES * 32 / 256, 256>>>(edge_attr, enc_w, enc_b);
    degree_kernel<<<(NEDGES + 255) / 256, 256>>>();
    cntinv_kernel<<<(NNODES + 255) / 256, 256>>>();

    for (int l = 0; l < NLAYERS; l++) {
        edge_kernel<<<NEDGES / 64, 256, SMEM_BYTES>>>(
            ew1 + (size_t)l * 384 * HID, eb1 + (size_t)l * HID,
            ew2 + (size_t)l * HID * HID, eb2 + (size_t)l * HID);
        node_kernel<<<(NNODES + 63) / 64, 256, SMEM_BYTES>>>(
            nw1 + (size_t)l * 256 * HID, nb1 + (size_t)l * HID,
            nw2 + (size_t)l * HID * HID, nb2 + (size_t)l * HID);
    }

    decode_kernel<<<(NNODES * 32 + 255) / 256, 256>>>(dec_w, dec_b, (float*)d_out);
}

// round 5
// speedup vs baseline: 1.5799x; 1.5799x over previous
#include <cuda_runtime.h>
#include <cuda_bf16.h>
#include <cstdint>

#define HID      128
#define NNODES   50000
#define NEDGES   640000
#define NLAYERS  6

// ---------------- scratch (device globals: no allocation allowed) ----------
__device__ float g_x[(size_t)NNODES * HID];      // node features
__device__ float g_sum[(size_t)NNODES * HID];    // scatter-sum accumulator
__device__ float g_ef[(size_t)NEDGES * HID];     // edge features
__device__ float g_pa[(size_t)NNODES * HID];     // x @ W1a  (dst projection)
__device__ float g_pb[(size_t)NNODES * HID];     // x @ W1b  (src projection)
__device__ float g_cnt[NNODES];                  // in-degree
__device__ float g_cntinv[NNODES];               // 1/max(deg,1)
__device__ int   g_src[NEDGES];                  // normalized int32 indices
__device__ int   g_dst[NEDGES];
__device__ unsigned int g_idx_is_i32;            // dtype flag

// ---------------- zero-fill (memset nodes invalid on device globals) --------
__global__ void zero_kernel() {
    size_t i = (size_t)blockIdx.x * blockDim.x + threadIdx.x;
    size_t n4 = (size_t)NNODES * HID / 4;
    if (i < n4) {
        ((float4*)g_x)[i]   = make_float4(0.f, 0.f, 0.f, 0.f);
        ((float4*)g_sum)[i] = make_float4(0.f, 0.f, 0.f, 0.f);
    }
    if (i < NNODES) g_cnt[i] = 0.0f;
    if (i == 0)     g_idx_is_i32 = 0u;
}

// ---------------- edge_index dtype detection + normalization ----------------
__global__ void detect_idx_kernel(const unsigned int* __restrict__ w) {
    int i = blockIdx.x * blockDim.x + threadIdx.x;      // odd-word index
    unsigned int v = w[2 * i + 1];
    if (v != 0u) atomicOr(&g_idx_is_i32, 1u);
}

__global__ void convert_idx_kernel(const void* __restrict__ ei) {
    int e = blockIdx.x * blockDim.x + threadIdx.x;
    if (e >= NEDGES) return;
    if (g_idx_is_i32) {
        const int* p = (const int*)ei;
        g_src[e] = p[e];
        g_dst[e] = p[NEDGES + e];
    } else {
        const long long* p = (const long long*)ei;
        g_src[e] = (int)p[e];
        g_dst[e] = (int)p[NEDGES + e];
    }
}

// ---------------- packed f32x2 helpers -------------------------------------
__device__ __forceinline__ void ffma2(unsigned long long& acc,
                                      unsigned long long a,
                                      unsigned long long b) {
    asm("fma.rn.f32x2 %0, %1, %2, %0;" : "+l"(acc) : "l"(a), "l"(b));
}
__device__ __forceinline__ unsigned long long dup2(float x) {
    unsigned long long r;
    asm("mov.b64 %0, {%1, %1};" : "=l"(r) : "f"(x));
    return r;
}
__device__ __forceinline__ float2 unpack2(unsigned long long v) {
    float2 f;
    asm("mov.b64 {%0, %1}, %2;" : "=f"(f.x), "=f"(f.y) : "l"(v));
    return f;
}

// ---------------- 64x128 += Asm[64x128] @ Wsm[128x128] ----------------------
// Thread (ty in 0..7, tx in 0..31) owns rows ty*8..ty*8+7, cols tx*4..tx*4+3.
__device__ __forceinline__ void gemm128(unsigned long long acc[8][2],
                                        const float* Asm, const float* Wsm,
                                        int ty, int tx) {
    const float4*      A4  = (const float4*)Asm;
    const ulonglong2*  W2v = (const ulonglong2*)Wsm;
    #pragma unroll 4
    for (int k = 0; k < 128; k += 4) {
        ulonglong2 w[4];
        #pragma unroll
        for (int kk = 0; kk < 4; kk++) w[kk] = W2v[(k + kk) * 32 + tx];
        #pragma unroll
        for (int e = 0; e < 8; e++) {
            float4 a = A4[(ty * 8 + e) * 32 + (k >> 2)];
            unsigned long long ap;
            ap = dup2(a.x); ffma2(acc[e][0], ap, w[0].x); ffma2(acc[e][1], ap, w[0].y);
            ap = dup2(a.y); ffma2(acc[e][0], ap, w[1].x); ffma2(acc[e][1], ap, w[1].y);
            ap = dup2(a.z); ffma2(acc[e][0], ap, w[2].x); ffma2(acc[e][1], ap, w[2].y);
            ap = dup2(a.w); ffma2(acc[e][0], ap, w[3].x); ffma2(acc[e][1], ap, w[3].y);
        }
    }
}

// ---------------- encoder: ef = edge_attr @ enc_w + enc_b ------------------
__global__ void encode_kernel(const float* __restrict__ ea,
                              const float* __restrict__ w,
                              const float* __restrict__ b) {
    int gid = blockIdx.x * 256 + threadIdx.x;   // NEDGES*32 threads exactly
    int e = gid >> 5, q = gid & 31;
    if (e >= NEDGES) return;
    float a0 = __ldg(ea + (size_t)e * 3 + 0);
    float a1 = __ldg(ea + (size_t)e * 3 + 1);
    float a2 = __ldg(ea + (size_t)e * 3 + 2);
    float4 w0 = __ldg((const float4*)w + q);
    float4 w1 = __ldg((const float4*)(w + 128) + q);
    float4 w2 = __ldg((const float4*)(w + 256) + q);
    float4 bb = __ldg((const float4*)b + q);
    float4 r;
    r.x = bb.x + a0 * w0.x + a1 * w1.x + a2 * w2.x;
    r.y = bb.y + a0 * w0.y + a1 * w1.y + a2 * w2.y;
    r.z = bb.z + a0 * w0.z + a1 * w1.z + a2 * w2.z;
    r.w = bb.w + a0 * w0.w + a1 * w1.w + a2 * w2.w;
    ((float4*)g_ef)[(size_t)e * 32 + q] = r;
}

// ---------------- in-degree -------------------------------------------------
__global__ void degree_kernel() {
    int e = blockIdx.x * 256 + threadIdx.x;
    if (e < NEDGES) {
        int d = g_dst[e];
        if (d >= 0 && d < NNODES) atomicAdd(&g_cnt[d], 1.0f);
    }
}
__global__ void cntinv_kernel() {
    int n = blockIdx.x * 256 + threadIdx.x;
    if (n < NNODES) g_cntinv[n] = 1.0f / fmaxf(g_cnt[n], 1.0f);
}

// ---------------- per-node projections: Pa = x@W1a, Pb = x@W1b --------------
// W1a = edge_w1 rows [0,128)  (multiplies x[dst])
// W1b = edge_w1 rows [128,256) (multiplies x[src])
__global__ void __launch_bounds__(256, 2)
proj_kernel(const float* __restrict__ wa, const float* __restrict__ wb) {
    extern __shared__ float sm[];
    float* Asm = sm;            // 64*128 floats
    float* Wsm = sm + 8192;     // 128*128 floats

    int tid = threadIdx.x, ty = tid >> 5, tx = tid & 31;
    int n0 = blockIdx.x * 64;

    // stage x tile (clamped)
    #pragma unroll
    for (int i = 0; i < 8; i++) {
        int lin = tid + i * 256;
        int r = lin >> 5, col = lin & 31;
        int n = n0 + r; if (n >= NNODES) n = NNODES - 1;
        ((float4*)Asm)[lin] = ((const float4*)(g_x + (size_t)n * HID))[col];
    }
    #pragma unroll
    for (int i = 0; i < 16; i++) {
        int lin = tid + i * 256;
        ((float4*)Wsm)[lin] = ((const float4*)wa)[lin];
    }
    __syncthreads();

    unsigned long long acc[8][2];
    #pragma unroll
    for (int e = 0; e < 8; e++) { acc[e][0] = 0ull; acc[e][1] = 0ull; }
    gemm128(acc, Asm, Wsm, ty, tx);

    #pragma unroll
    for (int e = 0; e < 8; e++) {
        int gn = n0 + ty * 8 + e;
        if (gn < NNODES) {
            float2 p0 = unpack2(acc[e][0]), p1 = unpack2(acc[e][1]);
            ((float4*)(g_pa + (size_t)gn * HID))[tx] = make_float4(p0.x, p0.y, p1.x, p1.y);
        }
        acc[e][0] = 0ull; acc[e][1] = 0ull;
    }
    __syncthreads();
    #pragma unroll
    for (int i = 0; i < 16; i++) {
        int lin = tid + i * 256;
        ((float4*)Wsm)[lin] = ((const float4*)wb)[lin];
    }
    __syncthreads();
    gemm128(acc, Asm, Wsm, ty, tx);

    #pragma unroll
    for (int e = 0; e < 8; e++) {
        int gn = n0 + ty * 8 + e;
        if (gn >= NNODES) continue;
        float2 p0 = unpack2(acc[e][0]), p1 = unpack2(acc[e][1]);
        ((float4*)(g_pb + (size_t)gn * HID))[tx] = make_float4(p0.x, p0.y, p1.x, p1.y);
    }
}

// ---------------- fused edge MLP + residual + scatter -----------------------
// h = relu(ef@W1c + Pa[dst] + Pb[src] + b1);  m = h@W2 + b2
__global__ void __launch_bounds__(256, 2)
edge_kernel(const float* __restrict__ w1c, const float* __restrict__ b1,
            const float* __restrict__ w2, const float* __restrict__ b2) {
    extern __shared__ float sm[];
    float* Asm = sm;            // 64*128 floats (ef tile, then hidden H)
    float* Wsm = sm + 8192;     // 128*128 floats
    __shared__ int   s_src[64], s_dst[64];
    __shared__ float s_b1[128], s_b2[128];

    int tid = threadIdx.x, ty = tid >> 5, tx = tid & 31;
    int e0 = blockIdx.x * 64;

    if (tid < 64) {
        s_src[tid] = g_src[e0 + tid];
        s_dst[tid] = g_dst[e0 + tid];
    }
    if (tid < 128) { s_b1[tid] = b1[tid]; s_b2[tid] = b2[tid]; }

    // stage ef tile + W1c
    #pragma unroll
    for (int i = 0; i < 8; i++) {
        int lin = tid + i * 256;
        int r = lin >> 5, col = lin & 31;
        ((float4*)Asm)[lin] = ((const float4*)(g_ef + (size_t)(e0 + r) * HID))[col];
    }
    #pragma unroll
    for (int i = 0; i < 16; i++) {
        int lin = tid + i * 256;
        ((float4*)Wsm)[lin] = ((const float4*)w1c)[lin];
    }
    __syncthreads();

    unsigned long long acc[8][2];
    #pragma unroll
    for (int e = 0; e < 8; e++) { acc[e][0] = 0ull; acc[e][1] = 0ull; }

    // ---- GEMM1: ef @ W1c  (K=128)
    gemm128(acc, Asm, Wsm, ty, tx);
    __syncthreads();

    // ---- stage W2 (Wsm free now)
    #pragma unroll
    for (int i = 0; i < 16; i++) {
        int lin = tid + i * 256;
        ((float4*)Wsm)[lin] = ((const float4*)w2)[lin];
    }

    // ---- h = relu(acc + Pa[dst] + Pb[src] + b1) -> Asm
    #pragma unroll
    for (int e = 0; e < 8; e++) {
        int le = ty * 8 + e;
        float4 pa = ((const float4*)(g_pa + (size_t)s_dst[le] * HID))[tx];
        float4 pb = ((const float4*)(g_pb + (size_t)s_src[le] * HID))[tx];
        float2 p0 = unpack2(acc[e][0]), p1 = unpack2(acc[e][1]);
        float4 h;
        h.x = fmaxf(p0.x + pa.x + pb.x + s_b1[tx * 4 + 0], 0.0f);
        h.y = fmaxf(p0.y + pa.y + pb.y + s_b1[tx * 4 + 1], 0.0f);
        h.z = fmaxf(p1.x + pa.z + pb.z + s_b1[tx * 4 + 2], 0.0f);
        h.w = fmaxf(p1.y + pa.w + pb.w + s_b1[tx * 4 + 3], 0.0f);
        ((float4*)Asm)[le * 32 + tx] = h;
        acc[e][0] = 0ull; acc[e][1] = 0ull;
    }
    __syncthreads();

    // ---- GEMM2: h @ W2  (K=128)
    gemm128(acc, Asm, Wsm, ty, tx);

    // ---- epilogue: m = acc + b2 ; ef += m ; scatter-add to g_sum[dst]
    #pragma unroll
    for (int e = 0; e < 8; e++) {
        int le = ty * 8 + e;
        int ge = e0 + le;
        float2 p0 = unpack2(acc[e][0]), p1 = unpack2(acc[e][1]);
        float4 m;
        m.x = p0.x + s_b2[tx * 4 + 0];
        m.y = p0.y + s_b2[tx * 4 + 1];
        m.z = p1.x + s_b2[tx * 4 + 2];
        m.w = p1.y + s_b2[tx * 4 + 3];

        float4* efp = (float4*)(g_ef + (size_t)ge * HID) + tx;
        float4 eo = *efp;
        eo.x += m.x; eo.y += m.y; eo.z += m.z; eo.w += m.w;
        *efp = eo;

        float* sp = g_sum + (size_t)s_dst[le] * HID + tx * 4;
        atomicAdd(sp + 0, m.x);
        atomicAdd(sp + 1, m.y);
        atomicAdd(sp + 2, m.z);
        atomicAdd(sp + 3, m.w);
    }
}

// ---------------- fused node MLP + residual ---------------------------------
// input = [x | mean_aggr]  (2 K-chunks of 128); consume-and-clear g_sum.
__global__ void __launch_bounds__(256, 2)
node_kernel(const float* __restrict__ w1, const float* __restrict__ b1,
            const float* __restrict__ w2, const float* __restrict__ b2) {
    extern __shared__ float sm[];
    float* Asm = sm;
    float* Wsm = sm + 8192;
    __shared__ float s_scale[64];
    __shared__ float s_b1[128], s_b2[128];

    int tid = threadIdx.x, ty = tid >> 5, tx = tid & 31;
    int n0 = blockIdx.x * 64;

    if (tid < 64) {
        int n = n0 + tid;
        s_scale[tid] = (n < NNODES) ? g_cntinv[n] : 0.0f;
    }
    if (tid < 128) { s_b1[tid] = b1[tid]; s_b2[tid] = b2[tid]; }

    unsigned long long acc[8][2];
    #pragma unroll
    for (int e = 0; e < 8; e++) { acc[e][0] = 0ull; acc[e][1] = 0ull; }

    for (int c = 0; c < 2; c++) {
        __syncthreads();
        #pragma unroll
        for (int i = 0; i < 8; i++) {
            int lin = tid + i * 256;
            int r = lin >> 5, col = lin & 31;
            int n = n0 + r;
            bool valid = (n < NNODES);
            if (!valid) n = NNODES - 1;
            float4 v;
            if (c == 0) {
                v = ((const float4*)(g_x + (size_t)n * HID))[col];
            } else {
                v = ((const float4*)(g_sum + (size_t)n * HID))[col];
                float s = s_scale[r];
                v.x *= s; v.y *= s; v.z *= s; v.w *= s;
                if (valid)
                    ((float4*)(g_sum + (size_t)n * HID))[col] =
                        make_float4(0.f, 0.f, 0.f, 0.f);
            }
            ((float4*)Asm)[lin] = v;
        }
        const float4* wg = (const float4*)(w1 + (size_t)c * 128 * HID);
        #pragma unroll
        for (int i = 0; i < 16; i++) {
            int lin = tid + i * 256;
            ((float4*)Wsm)[lin] = wg[lin];
        }
        __syncthreads();
        gemm128(acc, Asm, Wsm, ty, tx);
    }
    __syncthreads();

    #pragma unroll
    for (int e = 0; e < 8; e++) {
        float2 p0 = unpack2(acc[e][0]), p1 = unpack2(acc[e][1]);
        float4 h;
        h.x = fmaxf(p0.x + s_b1[tx * 4 + 0], 0.0f);
        h.y = fmaxf(p0.y + s_b1[tx * 4 + 1], 0.0f);
        h.z = fmaxf(p1.x + s_b1[tx * 4 + 2], 0.0f);
        h.w = fmaxf(p1.y + s_b1[tx * 4 + 3], 0.0f);
        ((float4*)Asm)[(ty * 8 + e) * 32 + tx] = h;
        acc[e][0] = 0ull; acc[e][1] = 0ull;
    }
    #pragma unroll
    for (int i = 0; i < 16; i++) {
        int lin = tid + i * 256;
        ((float4*)Wsm)[lin] = ((const float4*)w2)[lin];
    }
    __syncthreads();

    gemm128(acc, Asm, Wsm, ty, tx);

    #pragma unroll
    for (int e = 0; e < 8; e++) {
        int gn = n0 + ty * 8 + e;
        if (gn >= NNODES) continue;
        float2 p0 = unpack2(acc[e][0]), p1 = unpack2(acc[e][1]);
        float4* xp = (float4*)(g_x + (size_t)gn * HID) + tx;
        float4 xo = *xp;
        xo.x += p0.x + s_b2[tx * 4 + 0];
        xo.y += p0.y + s_b2[tx * 4 + 1];
        xo.z += p1.x + s_b2[tx * 4 + 2];
        xo.w += p1.y + s_b2[tx * 4 + 3];
        *xp = xo;
    }
}

// ---------------- decoder + row-normalize -----------------------------------
__global__ void decode_kernel(const float* __restrict__ dw,
                              const float* __restrict__ db,
                              float* __restrict__ out) {
    int warp = (blockIdx.x * blockDim.x + threadIdx.x) >> 5;
    int lane = threadIdx.x & 31;
    if (warp >= NNODES) return;
    const float* xr = g_x + (size_t)warp * HID;
    float a0 = 0.f, a1 = 0.f, a2 = 0.f;
    #pragma unroll
    for (int i = 0; i < 4; i++) {
        int k = lane + i * 32;
        float xv = xr[k];
        a0 += xv * __ldg(dw + k * 3 + 0);
        a1 += xv * __ldg(dw + k * 3 + 1);
        a2 += xv * __ldg(dw + k * 3 + 2);
    }
    #pragma unroll
    for (int o = 16; o; o >>= 1) {
        a0 += __shfl_xor_sync(0xffffffffu, a0, o);
        a1 += __shfl_xor_sync(0xffffffffu, a1, o);
        a2 += __shfl_xor_sync(0xffffffffu, a2, o);
    }
    if (lane == 0) {
        a0 += __ldg(db + 0); a1 += __ldg(db + 1); a2 += __ldg(db + 2);
        float nrm = sqrtf(a0 * a0 + a1 * a1 + a2 * a2);
        float inv = 1.0f / fmaxf(nrm, 1e-12f);
        out[(size_t)warp * 3 + 0] = a0 * inv;
        out[(size_t)warp * 3 + 1] = a1 * inv;
        out[(size_t)warp * 3 + 2] = a2 * inv;
    }
}

// ---------------- launcher ---------------------------------------------------
extern "C" void kernel_launch(void* const* d_in, const int* in_sizes, int n_in,
                              void* d_out, int out_size) {
    (void)in_sizes; (void)n_in; (void)out_size;
    // metadata order: pos, edge_attr, edge_index, enc_w, enc_b, dec_w, dec_b,
    //                 edge_w1, edge_b1, edge_w2, edge_b2,
    //                 node_w1, node_b1, node_w2, node_b2
    const float* edge_attr = (const float*)d_in[1];
    const void*  ei        = d_in[2];
    const float* enc_w = (const float*)d_in[3];
    const float* enc_b = (const float*)d_in[4];
    const float* dec_w = (const float*)d_in[5];
    const float* dec_b = (const float*)d_in[6];
    const float* ew1   = (const float*)d_in[7];
    const float* eb1   = (const float*)d_in[8];
    const float* ew2   = (const float*)d_in[9];
    const float* eb2   = (const float*)d_in[10];
    const float* nw1   = (const float*)d_in[11];
    const float* nb1   = (const float*)d_in[12];
    const float* nw2   = (const float*)d_in[13];
    const float* nb2   = (const float*)d_in[14];

    const int SMEM_BYTES = (8192 + 16384) * sizeof(float);   // 96 KB
    cudaFuncSetAttribute(proj_kernel, cudaFuncAttributeMaxDynamicSharedMemorySize, SMEM_BYTES);
    cudaFuncSetAttribute(edge_kernel, cudaFuncAttributeMaxDynamicSharedMemorySize, SMEM_BYTES);
    cudaFuncSetAttribute(node_kernel, cudaFuncAttributeMaxDynamicSharedMemorySize, SMEM_BYTES);
    cudaGetLastError();   // clear any soft error

    {
        size_t n4 = (size_t)NNODES * HID / 4;   // 1.6M threads
        zero_kernel<<<(unsigned)((n4 + 255) / 256), 256>>>();
    }

    detect_idx_kernel<<<NEDGES / 256, 256>>>((const unsigned int*)ei);
    convert_idx_kernel<<<(NEDGES + 255) / 256, 256>>>(ei);

    encode_kernel<<<NEDGES * 32 / 256, 256>>>(edge_attr, enc_w, enc_b);
    degree_kernel<<<(NEDGES + 255) / 256, 256>>>();
    cntinv_kernel<<<(NNODES + 255) / 256, 256>>>();

    for (int l = 0; l < NLAYERS; l++) {
        const float* w1 = ew1 + (size_t)l * 384 * HID;
        proj_kernel<<<(NNODES + 63) / 64, 256, SMEM_BYTES>>>(
            w1,                    // W1a: rows [0,128)   -> x[dst]
            w1 + 128 * HID);       // W1b: rows [128,256) -> x[src]
        edge_kernel<<<NEDGES / 64, 256, SMEM_BYTES>>>(
            w1 + 256 * HID,        // W1c: rows [256,384) -> ef
            eb1 + (size_t)l * HID,
            ew2 + (size_t)l * HID * HID, eb2 + (size_t)l * HID);
        node_kernel<<<(NNODES + 63) / 64, 256, SMEM_BYTES>>>(
            nw1 + (size_t)l * 256 * HID, nb1 + (size_t)l * HID,
            nw2 + (size_t)l * HID * HID, nb2 + (size_t)l * HID);
    }

    decode_kernel<<<(NNODES * 32 + 255) / 256, 256>>>(dec_w, dec_b, (float*)d_out);
}